// round 1
// baseline (speedup 1.0000x reference)
#include <cuda_runtime.h>
#include <math.h>

#define NB   300
#define BATCH 8
#define RSEL 36
#define NW   10     // ceil(300/32) suppression-mask words
#define CCH  256
#define GRID 14     // OUT*SR
#define CONF_THR 0.3f
#define IOU_THR  0.7f

// Scratch for inter-kernel state (no allocations allowed)
__device__ float g_sel_boxes[BATCH * RSEL * 4];
__device__ int   g_sel_valid[BATCH * RSEL];
__device__ int   g_sel_lv[BATCH * RSEL];

// ---------------------------------------------------------------------------
// Kernel A: per-batch NMS + selection + FPN level. One block per batch.
// ---------------------------------------------------------------------------
__global__ void nms_select_kernel(const float* __restrict__ boxes,
                                  const float* __restrict__ scores)
{
    const int b = blockIdx.x;
    const int t = threadIdx.x;

    __shared__ float s_raw[NB];            // thresholded scores (orig order)
    __shared__ int   s_order[NB];          // order[rank] = orig index
    __shared__ float sbx[NB], sby[NB], sbx2[NB], sby2[NB]; // sorted boxes
    __shared__ float s_ss[NB];             // sorted scores
    __shared__ unsigned s_sup[NB][NW];     // suppression bitmask rows
    __shared__ unsigned s_keepw[NW];
    __shared__ int   s_sel[RSEL];

    // 1) thresholded scores
    for (int i = t; i < NB; i += blockDim.x) {
        float sc = scores[b * NB + i];
        s_raw[i] = (sc > CONF_THR) ? sc : -INFINITY;
    }
    __syncthreads();

    // 2) stable descending rank sort (O(N^2), N=300 — trivial)
    for (int i = t; i < NB; i += blockDim.x) {
        float si = s_raw[i];
        int rank = 0;
        for (int j = 0; j < NB; j++) {
            float sj = s_raw[j];
            if (sj > si || (sj == si && j < i)) rank++;
        }
        s_order[rank] = i;
    }
    __syncthreads();

    // 3) gather sorted boxes/scores
    for (int r = t; r < NB; r += blockDim.x) {
        int i = s_order[r];
        const float* bp = boxes + ((size_t)b * NB + i) * 4;
        sbx[r]  = bp[0];
        sby[r]  = bp[1];
        sbx2[r] = bp[2];
        sby2[r] = bp[3];
        s_ss[r] = s_raw[i];
    }
    __syncthreads();

    // 4) suppression bitmask: row i, bit j set iff j>i && iou(i,j) > thr
    for (int i = t; i < NB; i += blockDim.x) {
        float ax1 = sbx[i], ay1 = sby[i], ax2 = sbx2[i], ay2 = sby2[i];
        float area_a = (ax2 - ax1) * (ay2 - ay1);
        for (int w = 0; w < NW; w++) {
            unsigned bits = 0;
            #pragma unroll 4
            for (int k = 0; k < 32; k++) {
                int j = w * 32 + k;
                if (j < NB && j > i) {
                    float bx1 = sbx[j], by1 = sby[j], bx2 = sbx2[j], by2 = sby2[j];
                    float area_b = (bx2 - bx1) * (by2 - by1);
                    float ltx = fmaxf(ax1, bx1);
                    float lty = fmaxf(ay1, by1);
                    float rbx = fminf(ax2, bx2);
                    float rby = fminf(ay2, by2);
                    float iw = fmaxf(rbx - ltx, 0.0f);
                    float ih = fmaxf(rby - lty, 0.0f);
                    float inter = iw * ih;
                    float iou = inter / (area_a + area_b - inter + 1e-9f);
                    if (iou > IOU_THR) bits |= (1u << k);
                }
            }
            s_sup[i][w] = bits;
        }
    }
    // init keep bits from validity
    if (t < NW) {
        unsigned bits = 0;
        for (int k = 0; k < 32; k++) {
            int j = t * 32 + k;
            if (j < NB && s_ss[j] > -INFINITY) bits |= (1u << k);
        }
        s_keepw[t] = bits;
    }
    __syncthreads();

    // 5) sequential greedy suppression, warp 0 only (lanes own keep-words)
    if (t < 32) {
        unsigned keepw = (t < NW) ? s_keepw[t] : 0u;
        for (int i = 0; i < NB; i++) {
            unsigned w = __shfl_sync(0xffffffffu, keepw, i >> 5);
            if ((w >> (i & 31)) & 1u) {
                if (t < NW) keepw &= ~s_sup[i][t];
            }
        }
        if (t < NW) s_keepw[t] = keepw;
    }
    __syncthreads();

    // 6) stable partition: kept (in order) first, then suppressed (in order)
    if (t == 0) {
        int cnt = 0;
        for (int j = 0; j < NB && cnt < RSEL; j++)
            if ((s_keepw[j >> 5] >> (j & 31)) & 1u) s_sel[cnt++] = j;
        for (int j = 0; j < NB && cnt < RSEL; j++)
            if (!((s_keepw[j >> 5] >> (j & 31)) & 1u)) s_sel[cnt++] = j;
    }
    __syncthreads();

    // 7) emit selected boxes, validity, FPN level
    if (t < RSEL) {
        int j = s_sel[t];
        float x1 = sbx[j], y1 = sby[j], x2 = sbx2[j], y2 = sby2[j];
        int base = b * RSEL + t;
        g_sel_boxes[base * 4 + 0] = x1;
        g_sel_boxes[base * 4 + 1] = y1;
        g_sel_boxes[base * 4 + 2] = x2;
        g_sel_boxes[base * 4 + 3] = y2;
        g_sel_valid[base] = (s_keepw[j >> 5] >> (j & 31)) & 1u;
        float dx = x2 - x1, dy = y2 - y1;
        float sz = sqrtf(fmaxf(dx * dx + dy * dy, 1e-12f));
        float lvf = floorf(4.0f + log2f(sz / 224.0f * 4.0f));
        lvf = fminf(fmaxf(lvf, 2.0f), 5.0f);
        g_sel_lv[base] = (int)lvf - 2;
    }
}

// ---------------------------------------------------------------------------
// Kernel B: ROI-align pooling. One block per (box, batch), thread = channel.
// ---------------------------------------------------------------------------
__global__ void roi_pool_kernel(const float* __restrict__ f0,
                                const float* __restrict__ f1,
                                const float* __restrict__ f2,
                                const float* __restrict__ f3,
                                float* __restrict__ out)
{
    const int r = blockIdx.x;
    const int b = blockIdx.y;
    const int c = threadIdx.x;         // 0..255
    const int idx = b * RSEL + r;

    __shared__ float s_box[4];
    __shared__ int   s_valid, s_lv;
    __shared__ float s_lx[GRID], s_ly[GRID];
    __shared__ int   s_x0[GRID], s_x1[GRID], s_y0[GRID], s_y1[GRID];
    __shared__ int   s_ox[GRID], s_oy[GRID];

    if (c == 0) { s_valid = g_sel_valid[idx]; s_lv = g_sel_lv[idx]; }
    if (c < 4)  s_box[c] = g_sel_boxes[idx * 4 + c];
    __syncthreads();

    float* outp = out + (size_t)idx * CCH;
    if (!s_valid) { outp[c] = 0.0f; return; }

    const int lv = s_lv;
    const int H = 200 >> lv;           // square maps: W == H
    const float* feat = (lv == 0) ? f0 : (lv == 1) ? f1 : (lv == 2) ? f2 : f3;

    if (c < GRID) {
        // X samples
        float x1 = s_box[0], x2 = s_box[2];
        float rw = fmaxf(x2 - x1, 1.0f);
        float g = ((float)c + 0.5f) / (float)GRID;
        float X = x1 + rw * g;
        s_ox[c] = (X < -1.0f) || (X > (float)H);
        float x = fminf(fmaxf(X, 0.0f), (float)(H - 1));
        int x0 = (int)floorf(x);
        s_x0[c] = x0;
        s_x1[c] = min(x0 + 1, H - 1);
        s_lx[c] = x - (float)x0;
    } else if (c < 2 * GRID) {
        // Y samples
        int i = c - GRID;
        float y1 = s_box[1], y2 = s_box[3];
        float rh = fmaxf(y2 - y1, 1.0f);
        float g = ((float)i + 0.5f) / (float)GRID;
        float Y = y1 + rh * g;
        s_oy[i] = (Y < -1.0f) || (Y > (float)H);
        float y = fminf(fmaxf(Y, 0.0f), (float)(H - 1));
        int y0 = (int)floorf(y);
        s_y0[i] = y0;
        s_y1[i] = min(y0 + 1, H - 1);
        s_ly[i] = y - (float)y0;
    }
    __syncthreads();

    const size_t hw = (size_t)H * (size_t)H;
    const float* base = feat + ((size_t)b * CCH + (size_t)c) * hw;

    float acc = 0.0f;
    for (int iy = 0; iy < GRID; iy++) {
        if (s_oy[iy]) continue;        // oob rows contribute 0
        const float* r0 = base + (size_t)s_y0[iy] * H;
        const float* r1 = base + (size_t)s_y1[iy] * H;
        float ly = s_ly[iy];
        float omly = 1.0f - ly;
        #pragma unroll
        for (int ix = 0; ix < GRID; ix++) {
            if (s_ox[ix]) continue;
            int x0 = s_x0[ix], x1i = s_x1[ix];
            float lx = s_lx[ix];
            float f00 = __ldg(r0 + x0);
            float f01 = __ldg(r0 + x1i);
            float f10 = __ldg(r1 + x0);
            float f11 = __ldg(r1 + x1i);
            // match reference 4-term bilinear expression
            acc += f00 * omly * (1.0f - lx) + f01 * omly * lx
                 + f10 * ly   * (1.0f - lx) + f11 * ly   * lx;
        }
    }
    outp[c] = acc * (1.0f / 196.0f);
}

// ---------------------------------------------------------------------------
extern "C" void kernel_launch(void* const* d_in, const int* in_sizes, int n_in,
                              void* d_out, int out_size)
{
    const float* boxes  = (const float*)d_in[0];
    const float* scores = (const float*)d_in[1];
    const float* f0     = (const float*)d_in[2];
    const float* f1     = (const float*)d_in[3];
    const float* f2     = (const float*)d_in[4];
    const float* f3     = (const float*)d_in[5];
    float* out = (float*)d_out;

    nms_select_kernel<<<BATCH, 320>>>(boxes, scores);
    roi_pool_kernel<<<dim3(RSEL, BATCH), CCH>>>(f0, f1, f2, f3, out);
}

// round 5
// speedup vs baseline: 1.6150x; 1.6150x over previous
#include <cuda_runtime.h>
#include <math.h>

#define NB    300
#define BATCH 8
#define RSEL  36
#define NW    10     // ceil(300/32) suppression-mask words
#define CCH   256
#define GRID  14     // OUT*SR
#define SPAN  64     // max ROI pixel span: worst case 58 (level 1), +margin
#define CONF_THR 0.3f
#define IOU_THR  0.7f

// Scratch for inter-kernel state (no allocations allowed)
__device__ float g_sel_boxes[BATCH * RSEL * 4];
__device__ int   g_sel_valid[BATCH * RSEL];
__device__ int   g_sel_lv[BATCH * RSEL];

// ---------------------------------------------------------------------------
// Kernel A: per-batch NMS + selection + FPN level. One block per batch.
// ---------------------------------------------------------------------------
__global__ void nms_select_kernel(const float* __restrict__ boxes,
                                  const float* __restrict__ scores)
{
    const int b = blockIdx.x;
    const int t = threadIdx.x;

    __shared__ float  s_raw[NB];           // thresholded scores (orig order)
    __shared__ int    s_order[NB];         // order[rank] = orig index
    __shared__ float4 s_box4[NB];          // sorted boxes
    __shared__ float  s_area[NB];          // sorted box areas
    __shared__ float  s_ss[NB];            // sorted scores
    __shared__ unsigned s_sup[NB][NW];     // suppression bitmask rows
    __shared__ unsigned s_keepw[NW];
    __shared__ int    s_sel[RSEL];

    // 1) thresholded scores
    for (int i = t; i < NB; i += blockDim.x) {
        float sc = scores[b * NB + i];
        s_raw[i] = (sc > CONF_THR) ? sc : -INFINITY;
    }
    __syncthreads();

    // 2) stable descending rank sort (O(N^2), N=300 — trivial)
    for (int i = t; i < NB; i += blockDim.x) {
        float si = s_raw[i];
        int rank = 0;
        for (int j = 0; j < NB; j++) {
            float sj = s_raw[j];
            if (sj > si || (sj == si && j < i)) rank++;
        }
        s_order[rank] = i;
    }
    __syncthreads();

    // 3) gather sorted boxes/scores, precompute areas
    for (int r = t; r < NB; r += blockDim.x) {
        int i = s_order[r];
        float4 bb = ((const float4*)boxes)[(size_t)b * NB + i];
        s_box4[r] = bb;
        s_area[r] = (bb.z - bb.x) * (bb.w - bb.y);
        s_ss[r]   = s_raw[i];
    }
    __syncthreads();

    // 4) suppression bitmask: row i, bit j set iff j>i && iou(i,j) > thr
    for (int i = t; i < NB; i += blockDim.x) {
        float4 a = s_box4[i];
        float area_a = s_area[i];
        int w0 = i >> 5;
        for (int w = 0; w < NW; w++) {
            unsigned bits = 0;
            if (w >= w0) {
                int kstart = (w == w0) ? (i & 31) + 1 : 0;
                for (int k = kstart; k < 32; k++) {
                    int j = w * 32 + k;
                    if (j < NB) {
                        float4 bb = s_box4[j];
                        float area_b = s_area[j];
                        float ltx = fmaxf(a.x, bb.x);
                        float lty = fmaxf(a.y, bb.y);
                        float rbx = fminf(a.z, bb.z);
                        float rby = fminf(a.w, bb.w);
                        float iw = fmaxf(rbx - ltx, 0.0f);
                        float ih = fmaxf(rby - lty, 0.0f);
                        float inter = iw * ih;
                        float iou = inter / (area_a + area_b - inter + 1e-9f);
                        if (iou > IOU_THR) bits |= (1u << k);
                    }
                }
            }
            s_sup[i][w] = bits;
        }
    }
    // init keep bits from validity
    if (t < NW) {
        unsigned bits = 0;
        for (int k = 0; k < 32; k++) {
            int j = t * 32 + k;
            if (j < NB && s_ss[j] > -INFINITY) bits |= (1u << k);
        }
        s_keepw[t] = bits;
    }
    __syncthreads();

    // 5) sequential greedy suppression, warp 0 only (lanes own keep-words)
    if (t < 32) {
        unsigned keepw = (t < NW) ? s_keepw[t] : 0u;
        for (int i = 0; i < NB; i++) {
            unsigned w = __shfl_sync(0xffffffffu, keepw, i >> 5);
            if ((w >> (i & 31)) & 1u) {
                if (t < NW) keepw &= ~s_sup[i][t];
            }
        }
        if (t < NW) s_keepw[t] = keepw;
    }
    __syncthreads();

    // 6) stable partition: kept (in order) first, then suppressed (in order)
    if (t == 0) {
        int cnt = 0;
        for (int j = 0; j < NB && cnt < RSEL; j++)
            if ((s_keepw[j >> 5] >> (j & 31)) & 1u) s_sel[cnt++] = j;
        for (int j = 0; j < NB && cnt < RSEL; j++)
            if (!((s_keepw[j >> 5] >> (j & 31)) & 1u)) s_sel[cnt++] = j;
    }
    __syncthreads();

    // 7) emit selected boxes, validity, FPN level
    if (t < RSEL) {
        int j = s_sel[t];
        float4 bb = s_box4[j];
        int base = b * RSEL + t;
        g_sel_boxes[base * 4 + 0] = bb.x;
        g_sel_boxes[base * 4 + 1] = bb.y;
        g_sel_boxes[base * 4 + 2] = bb.z;
        g_sel_boxes[base * 4 + 3] = bb.w;
        g_sel_valid[base] = (s_keepw[j >> 5] >> (j & 31)) & 1u;
        float dx = bb.z - bb.x, dy = bb.w - bb.y;
        float sz = sqrtf(fmaxf(dx * dx + dy * dy, 1e-12f));
        float lvf = floorf(4.0f + log2f(sz / 224.0f * 4.0f));
        lvf = fminf(fmaxf(lvf, 2.0f), 5.0f);
        g_sel_lv[base] = (int)lvf - 2;
    }
}

// ---------------------------------------------------------------------------
// Kernel B: ROI-align pooling via separable coefficient form.
//   pooled[c] = sum_y cy[y] * sum_x cx[x] * feat[c, y, x]   over a small patch
// Grid: (RSEL, BATCH, 8 channel-groups). Block: 256 (8 warps, 4 channels each).
// Lanes: 16 x-positions x 2 y-phases -> coalesced row-segment loads.
// ---------------------------------------------------------------------------
__global__ void roi_pool_kernel(const float* __restrict__ f0,
                                const float* __restrict__ f1,
                                const float* __restrict__ f2,
                                const float* __restrict__ f3,
                                float* __restrict__ out)
{
    const int r  = blockIdx.x;
    const int b  = blockIdx.y;
    const int cg = blockIdx.z;        // channel group of 32
    const int tid = threadIdx.x;
    const int idx = b * RSEL + r;

    __shared__ float s_cx[SPAN], s_cy[SPAN];
    __shared__ int s_xlo, s_ylo, s_Lx, s_Ly, s_valid, s_lv;

    if (tid < SPAN) { s_cx[tid] = 0.0f; s_cy[tid] = 0.0f; }
    if (tid == 0) { s_valid = g_sel_valid[idx]; s_lv = g_sel_lv[idx]; }
    __syncthreads();

    float* outp = out + (size_t)idx * CCH + cg * 32;
    if (!s_valid) {
        if (tid < 32) outp[tid] = 0.0f;
        return;
    }

    const int lv = s_lv;
    const int H = 200 >> lv;          // square maps

    // Build separable coefficient vectors (thread 0: X, thread 32: Y).
    if (tid == 0) {
        float x1 = g_sel_boxes[idx * 4 + 0], x2 = g_sel_boxes[idx * 4 + 2];
        float rw = fmaxf(x2 - x1, 1.0f);
        int lo = 1 << 30, hi = -(1 << 30);
        #pragma unroll
        for (int ix = 0; ix < GRID; ix++) {
            float g = ((float)ix + 0.5f) / (float)GRID;
            float X = x1 + rw * g;
            if (X < -1.0f || X > (float)H) continue;
            float x = fminf(fmaxf(X, 0.0f), (float)(H - 1));
            int x0 = (int)floorf(x);
            int x1i = min(x0 + 1, H - 1);
            lo = min(lo, x0); hi = max(hi, x1i);
        }
        if (lo > hi) { s_xlo = 0; s_Lx = 0; }
        else {
            s_xlo = lo; s_Lx = hi - lo + 1;
            #pragma unroll
            for (int ix = 0; ix < GRID; ix++) {
                float g = ((float)ix + 0.5f) / (float)GRID;
                float X = x1 + rw * g;
                if (X < -1.0f || X > (float)H) continue;
                float x = fminf(fmaxf(X, 0.0f), (float)(H - 1));
                int x0 = (int)floorf(x);
                int x1i = min(x0 + 1, H - 1);
                float lx = x - (float)x0;
                int i0 = x0 - lo, i1 = x1i - lo;
                if ((unsigned)i0 < SPAN) s_cx[i0] += 1.0f - lx;
                if ((unsigned)i1 < SPAN) s_cx[i1] += lx;
            }
        }
    } else if (tid == 32) {
        float y1 = g_sel_boxes[idx * 4 + 1], y2 = g_sel_boxes[idx * 4 + 3];
        float rh = fmaxf(y2 - y1, 1.0f);
        int lo = 1 << 30, hi = -(1 << 30);
        #pragma unroll
        for (int iy = 0; iy < GRID; iy++) {
            float g = ((float)iy + 0.5f) / (float)GRID;
            float Y = y1 + rh * g;
            if (Y < -1.0f || Y > (float)H) continue;
            float y = fminf(fmaxf(Y, 0.0f), (float)(H - 1));
            int y0 = (int)floorf(y);
            int y1i = min(y0 + 1, H - 1);
            lo = min(lo, y0); hi = max(hi, y1i);
        }
        if (lo > hi) { s_ylo = 0; s_Ly = 0; }
        else {
            s_ylo = lo; s_Ly = hi - lo + 1;
            #pragma unroll
            for (int iy = 0; iy < GRID; iy++) {
                float g = ((float)iy + 0.5f) / (float)GRID;
                float Y = y1 + rh * g;
                if (Y < -1.0f || Y > (float)H) continue;
                float y = fminf(fmaxf(Y, 0.0f), (float)(H - 1));
                int y0 = (int)floorf(y);
                int y1i = min(y0 + 1, H - 1);
                float ly = y - (float)y0;
                int i0 = y0 - lo, i1 = y1i - lo;
                if ((unsigned)i0 < SPAN) s_cy[i0] += 1.0f - ly;
                if ((unsigned)i1 < SPAN) s_cy[i1] += ly;
            }
        }
    }
    __syncthreads();

    const float* feat = (lv == 0) ? f0 : (lv == 1) ? f1 : (lv == 2) ? f2 : f3;
    const size_t hw = (size_t)H * (size_t)H;

    const int w    = tid >> 5;
    const int lane = tid & 31;
    const int xi = lane & 15;         // x within chunk of 16
    const int yh = lane >> 4;         // y phase (0/1)
    const int Lx = s_Lx, Ly = s_Ly, xlo = s_xlo, ylo = s_ylo;

    #pragma unroll
    for (int ci = 0; ci < 4; ci++) {
        const int c = w * 4 + ci;
        const float* base = feat + ((size_t)b * CCH + cg * 32 + c) * hw
                          + (size_t)ylo * H + xlo;
        float acc = 0.0f;
        for (int xb = xi; xb < Lx; xb += 16) {
            float s = 0.0f;
            #pragma unroll 2
            for (int yy = yh; yy < Ly; yy += 2)
                s += s_cy[yy] * __ldg(base + yy * H + xb);
            acc += s * s_cx[xb];
        }
        #pragma unroll
        for (int o = 16; o; o >>= 1)
            acc += __shfl_xor_sync(0xffffffffu, acc, o);
        if (lane == 0) outp[c] = acc * (1.0f / 196.0f);
    }
}

// ---------------------------------------------------------------------------
extern "C" void kernel_launch(void* const* d_in, const int* in_sizes, int n_in,
                              void* d_out, int out_size)
{
    const float* boxes  = (const float*)d_in[0];
    const float* scores = (const float*)d_in[1];
    const float* f0     = (const float*)d_in[2];
    const float* f1     = (const float*)d_in[3];
    const float* f2     = (const float*)d_in[4];
    const float* f3     = (const float*)d_in[5];
    float* out = (float*)d_out;

    nms_select_kernel<<<BATCH, 320>>>(boxes, scores);
    roi_pool_kernel<<<dim3(RSEL, BATCH, 8), 256>>>(f0, f1, f2, f3, out);
}

// round 6
// speedup vs baseline: 3.6045x; 2.2319x over previous
#include <cuda_runtime.h>
#include <math.h>

#define NB    300
#define BATCH 8
#define RSEL  36
#define NW    10
#define CCH   256
#define GRID  14
#define SPAN  64
#define NSEL  (BATCH * RSEL)
#define CONF_THR 0.3f
#define IOU_THR  0.7f

// Inter-kernel scratch (device globals; no allocations allowed)
__device__ float4   g_sbox[BATCH * NB];       // sorted boxes
__device__ unsigned g_vinit[BATCH * NW];      // initial keep words (validity)
__device__ unsigned g_sup[BATCH * NB * NW];   // suppression masks
__device__ float    g_cx[NSEL * SPAN];        // separable x coefficients
__device__ float    g_cy[NSEL * SPAN];        // separable y coefficients
__device__ int2     g_mx[NSEL];               // (xlo, Lx)
__device__ int2     g_my[NSEL];               // (ylo, Ly)
__device__ int2     g_mv[NSEL];               // (valid, lv)

// ---------------------------------------------------------------------------
// K1: per-batch threshold + stable rank sort + gather. 8 blocks x 320.
// ---------------------------------------------------------------------------
__global__ void k1_sort(const float* __restrict__ boxes,
                        const float* __restrict__ scores)
{
    const int b = blockIdx.x;
    const int t = threadIdx.x;

    __shared__ float s_raw[NB];
    __shared__ int   s_order[NB];
    __shared__ float s_ss[NB];

    for (int i = t; i < NB; i += blockDim.x) {
        float sc = scores[b * NB + i];
        s_raw[i] = (sc > CONF_THR) ? sc : -INFINITY;
    }
    __syncthreads();

    for (int i = t; i < NB; i += blockDim.x) {
        float si = s_raw[i];
        int rank = 0;
        for (int j = 0; j < NB; j++) {
            float sj = s_raw[j];
            if (sj > si || (sj == si && j < i)) rank++;
        }
        s_order[rank] = i;
    }
    __syncthreads();

    for (int r = t; r < NB; r += blockDim.x) {
        int i = s_order[r];
        g_sbox[b * NB + r] = ((const float4*)boxes)[(size_t)b * NB + i];
        s_ss[r] = s_raw[i];
    }
    __syncthreads();

    if (t < NW) {
        unsigned bits = 0;
        for (int k = 0; k < 32; k++) {
            int j = t * 32 + k;
            if (j < NB && s_ss[j] > -INFINITY) bits |= (1u << k);
        }
        g_vinit[b * NW + t] = bits;
    }
}

// ---------------------------------------------------------------------------
// K2: suppression masks, parallel across (word, batch). Grid (NW, BATCH) x 320.
// Block (w,b): thread i computes word w of row i (32 IoUs against smem-staged j).
// ---------------------------------------------------------------------------
__global__ void k2_mask()
{
    const int w = blockIdx.x;
    const int b = blockIdx.y;
    const int t = threadIdx.x;

    __shared__ float4 s_j[32];
    __shared__ float  s_ja[32];

    if (t < 32) {
        int j = w * 32 + t;
        float4 bb = (j < NB) ? g_sbox[b * NB + j] : make_float4(0, 0, 0, 0);
        s_j[t]  = bb;
        s_ja[t] = (bb.z - bb.x) * (bb.w - bb.y);
    }
    __syncthreads();

    const int i = t;
    if (i >= NB) return;

    unsigned bits = 0;
    if (w * 32 + 31 > i) {                    // word contains some j > i
        float4 a = g_sbox[b * NB + i];
        float area_a = (a.z - a.x) * (a.w - a.y);
        #pragma unroll 4
        for (int k = 0; k < 32; k++) {
            int j = w * 32 + k;
            if (j < NB && j > i) {
                float4 bb = s_j[k];
                float ltx = fmaxf(a.x, bb.x);
                float lty = fmaxf(a.y, bb.y);
                float rbx = fminf(a.z, bb.z);
                float rby = fminf(a.w, bb.w);
                float iw = fmaxf(rbx - ltx, 0.0f);
                float ih = fmaxf(rby - lty, 0.0f);
                float inter = iw * ih;
                float iou = inter / (area_a + s_ja[k] - inter + 1e-9f);
                if (iou > IOU_THR) bits |= (1u << k);
            }
        }
    }
    g_sup[(b * NB + i) * NW + w] = bits;
}

// ---------------------------------------------------------------------------
// K3: sequential suppression + stable selection + level + coefficient build.
// 8 blocks x 320.
// ---------------------------------------------------------------------------
__global__ void k3_final()
{
    const int b = blockIdx.x;
    const int t = threadIdx.x;

    __shared__ unsigned s_sup[NB][NW];          // 12 KB
    __shared__ unsigned s_keepw[NW];
    __shared__ int      s_sel[RSEL];
    __shared__ float4   s_selbox[RSEL];
    __shared__ float    s_coef[RSEL][2][SPAN];  // 18 KB

    for (int e = t; e < NB * NW; e += blockDim.x)
        ((unsigned*)s_sup)[e] = g_sup[b * NB * NW + e];
    if (t < NW) s_keepw[t] = g_vinit[b * NW + t];
    for (int e = t; e < RSEL * 2 * SPAN; e += blockDim.x)
        ((float*)s_coef)[e] = 0.0f;
    __syncthreads();

    // sequential greedy suppression (warp 0; lanes own keep words)
    if (t < 32) {
        unsigned keepw = (t < NW) ? s_keepw[t] : 0u;
        for (int i = 0; i < NB; i++) {
            unsigned wv = __shfl_sync(0xffffffffu, keepw, i >> 5);
            if ((wv >> (i & 31)) & 1u) {
                if (t < NW) keepw &= ~s_sup[i][t];
            }
        }
        if (t < NW) s_keepw[t] = keepw;
    }
    __syncthreads();

    // stable partition via bit scan: kept first, then suppressed
    if (t == 0) {
        int cnt = 0;
        for (int w = 0; w < NW && cnt < RSEL; w++) {
            unsigned bits = s_keepw[w];
            while (bits && cnt < RSEL) {
                int k = __ffs(bits) - 1; bits &= bits - 1;
                s_sel[cnt++] = w * 32 + k;
            }
        }
        for (int w = 0; w < NW && cnt < RSEL; w++) {
            unsigned bits = ~s_keepw[w];
            if (w == NW - 1) bits &= (1u << (NB - (NW - 1) * 32)) - 1;
            while (bits && cnt < RSEL) {
                int k = __ffs(bits) - 1; bits &= bits - 1;
                s_sel[cnt++] = w * 32 + k;
            }
        }
    }
    __syncthreads();

    if (t < RSEL) {
        int j = s_sel[t];
        float4 bb = g_sbox[b * NB + j];
        s_selbox[t] = bb;
        int valid = (s_keepw[j >> 5] >> (j & 31)) & 1u;
        float dx = bb.z - bb.x, dy = bb.w - bb.y;
        float sz = sqrtf(fmaxf(dx * dx + dy * dy, 1e-12f));
        float lvf = fminf(fmaxf(floorf(4.0f + log2f(sz / 224.0f * 4.0f)), 2.0f), 5.0f);
        g_mv[b * RSEL + t] = make_int2(valid, (int)lvf - 2);
    }
    __syncthreads();

    // coefficient build: task t -> (box r = t>>1, axis = t&1)
    if (t < 2 * RSEL) {
        const int r = t >> 1, axis = t & 1;
        float4 bb = s_selbox[r];
        float dx = bb.z - bb.x, dy = bb.w - bb.y;
        float sz = sqrtf(fmaxf(dx * dx + dy * dy, 1e-12f));
        float lvf = fminf(fmaxf(floorf(4.0f + log2f(sz / 224.0f * 4.0f)), 2.0f), 5.0f);
        int lv = (int)lvf - 2;
        int H = 200 >> lv;
        float c1 = axis ? bb.y : bb.x;
        float c2 = axis ? bb.w : bb.z;
        float rs = fmaxf(c2 - c1, 1.0f);

        int lo = 1 << 30, hi = -(1 << 30);
        #pragma unroll
        for (int s = 0; s < GRID; s++) {
            float g = ((float)s + 0.5f) / (float)GRID;
            float P = c1 + rs * g;
            if (P < -1.0f || P > (float)H) continue;
            float p = fminf(fmaxf(P, 0.0f), (float)(H - 1));
            int p0 = (int)floorf(p);
            int p1 = min(p0 + 1, H - 1);
            lo = min(lo, p0); hi = max(hi, p1);
        }
        int L;
        if (lo > hi) { lo = 0; L = 0; }
        else {
            L = hi - lo + 1;
            #pragma unroll
            for (int s = 0; s < GRID; s++) {
                float g = ((float)s + 0.5f) / (float)GRID;
                float P = c1 + rs * g;
                if (P < -1.0f || P > (float)H) continue;
                float p = fminf(fmaxf(P, 0.0f), (float)(H - 1));
                int p0 = (int)floorf(p);
                int p1 = min(p0 + 1, H - 1);
                float lp = p - (float)p0;
                s_coef[r][axis][p0 - lo] += 1.0f - lp;
                s_coef[r][axis][p1 - lo] += lp;
            }
        }
        if (axis) g_my[b * RSEL + r] = make_int2(lo, L);
        else      g_mx[b * RSEL + r] = make_int2(lo, L);
    }
    __syncthreads();

    // coalesced copy of coefficients to global
    for (int e = t; e < RSEL * 2 * SPAN; e += blockDim.x) {
        int r    = e / (2 * SPAN);
        int axis = (e >> 6) & 1;          // (e/SPAN)&1
        int k    = e & (SPAN - 1);
        float v  = s_coef[r][axis][k];
        if (axis) g_cy[(b * RSEL + r) * SPAN + k] = v;
        else      g_cx[(b * RSEL + r) * SPAN + k] = v;
    }
}

// ---------------------------------------------------------------------------
// K4: ROI pooling. Grid (RSEL, BATCH, 8 cg) x 256. Warp = 4 channels,
// lanes = 16 x-positions x 2 y-phases; 4-channel-interleaved loads for MLP.
// ---------------------------------------------------------------------------
__global__ void roi_pool_kernel(const float* __restrict__ f0,
                                const float* __restrict__ f1,
                                const float* __restrict__ f2,
                                const float* __restrict__ f3,
                                float* __restrict__ out)
{
    const int r   = blockIdx.x;
    const int b   = blockIdx.y;
    const int cg  = blockIdx.z;
    const int tid = threadIdx.x;
    const int idx = b * RSEL + r;

    __shared__ float s_cx[SPAN], s_cy[SPAN];
    __shared__ int s_xlo, s_ylo, s_Lx, s_Ly, s_valid, s_lv;

    if (tid < SPAN)            s_cx[tid]        = g_cx[idx * SPAN + tid];
    else if (tid < 2 * SPAN)   s_cy[tid - SPAN] = g_cy[idx * SPAN + tid - SPAN];
    else if (tid == 128) { int2 m = g_mx[idx]; s_xlo = m.x; s_Lx = m.y; }
    else if (tid == 129) { int2 m = g_my[idx]; s_ylo = m.x; s_Ly = m.y; }
    else if (tid == 130) { int2 m = g_mv[idx]; s_valid = m.x; s_lv = m.y; }
    __syncthreads();

    float* outp = out + (size_t)idx * CCH + cg * 32;
    if (!s_valid) {
        if (tid < 32) outp[tid] = 0.0f;
        return;
    }

    const int lv = s_lv;
    const int H  = 200 >> lv;
    const float* feat = (lv == 0) ? f0 : (lv == 1) ? f1 : (lv == 2) ? f2 : f3;
    const size_t hw = (size_t)H * (size_t)H;

    const int w    = tid >> 5;
    const int lane = tid & 31;
    const int xi   = lane & 15;
    const int yh   = lane >> 4;
    const int Lx = s_Lx, Ly = s_Ly;
    const int c0 = cg * 32 + w * 4;

    const float* bp = feat + ((size_t)b * CCH + c0) * hw
                    + (size_t)s_ylo * H + s_xlo;

    float a0 = 0.0f, a1 = 0.0f, a2 = 0.0f, a3 = 0.0f;
    for (int xb = xi; xb < Lx; xb += 16) {
        float cxv = s_cx[xb];
        float s0 = 0.0f, s1 = 0.0f, s2 = 0.0f, s3 = 0.0f;
        #pragma unroll 2
        for (int yy = yh; yy < Ly; yy += 2) {
            float cyv = s_cy[yy];
            const float* p = bp + (size_t)yy * H + xb;
            s0 += cyv * __ldg(p);
            s1 += cyv * __ldg(p + hw);
            s2 += cyv * __ldg(p + 2 * hw);
            s3 += cyv * __ldg(p + 3 * hw);
        }
        a0 += s0 * cxv; a1 += s1 * cxv; a2 += s2 * cxv; a3 += s3 * cxv;
    }

    #pragma unroll
    for (int o = 16; o; o >>= 1) {
        a0 += __shfl_xor_sync(0xffffffffu, a0, o);
        a1 += __shfl_xor_sync(0xffffffffu, a1, o);
        a2 += __shfl_xor_sync(0xffffffffu, a2, o);
        a3 += __shfl_xor_sync(0xffffffffu, a3, o);
    }
    if (lane == 0) {
        const float sc = 1.0f / 196.0f;
        float4 v = make_float4(a0 * sc, a1 * sc, a2 * sc, a3 * sc);
        *(float4*)(outp + w * 4) = v;
    }
}

// ---------------------------------------------------------------------------
extern "C" void kernel_launch(void* const* d_in, const int* in_sizes, int n_in,
                              void* d_out, int out_size)
{
    const float* boxes  = (const float*)d_in[0];
    const float* scores = (const float*)d_in[1];
    const float* f0     = (const float*)d_in[2];
    const float* f1     = (const float*)d_in[3];
    const float* f2     = (const float*)d_in[4];
    const float* f3     = (const float*)d_in[5];
    float* out = (float*)d_out;

    k1_sort<<<BATCH, 320>>>(boxes, scores);
    k2_mask<<<dim3(NW, BATCH), 320>>>();
    k3_final<<<BATCH, 320>>>();
    roi_pool_kernel<<<dim3(RSEL, BATCH, 8), 256>>>(f0, f1, f2, f3, out);
}